// round 5
// baseline (speedup 1.0000x reference)
#include <cuda_runtime.h>
#include <cstdint>

// ---------------- problem constants ----------------
#define BB 16
#define NN 1024
#define LL 7
#define DD 512
#define HH 8
#define HD 64
#define BND (BB * NN * DD)   // 8,388,608 floats

// ---------------- scratch (device globals; no allocations allowed) ----------
__device__ float g_agg[BND];   // lagged aggregation, later reused for O-proj
__device__ float g_Q[BND];
__device__ float g_K[BND];
__device__ float g_V[BND];
__device__ float g_att[BND];

// ---------------- packed fp32x2 helpers (FFMA2 path) ------------------------
__device__ __forceinline__ unsigned long long f32x2_dup(float x) {
    unsigned long long r; unsigned int xu = __float_as_uint(x);
    asm("mov.b64 %0, {%1, %1};" : "=l"(r) : "r"(xu));
    return r;
}
__device__ __forceinline__ unsigned long long f32x2_pack(float lo, float hi) {
    unsigned long long r;
    unsigned int a = __float_as_uint(lo), b = __float_as_uint(hi);
    asm("mov.b64 %0, {%1, %2};" : "=l"(r) : "r"(a), "r"(b));
    return r;
}
__device__ __forceinline__ void f32x2_unpack(unsigned long long v, float& lo, float& hi) {
    unsigned int a, b;
    asm("mov.b64 {%0, %1}, %2;" : "=r"(a), "=r"(b) : "l"(v));
    lo = __uint_as_float(a); hi = __uint_as_float(b);
}
__device__ __forceinline__ unsigned long long f32x2_fma(unsigned long long a,
                                                        unsigned long long b,
                                                        unsigned long long c) {
    unsigned long long d;
    asm("fma.rn.f32x2 %0, %1, %2, %3;" : "=l"(d) : "l"(a), "l"(b), "l"(c));
    return d;
}
__device__ __forceinline__ unsigned long long f32x2_mul(unsigned long long a,
                                                        unsigned long long b) {
    unsigned long long d;
    asm("mul.rn.f32x2 %0, %1, %2;" : "=l"(d) : "l"(a), "l"(b));
    return d;
}

// ---------------- kernel 1: lag softmax + weighted aggregation --------------
// out[b,n,d] = sum_l lf[b,n,l,d] * softmax(lw)[l]
__global__ void __launch_bounds__(256) lag_agg_kernel(
    const float* __restrict__ lf, const float* __restrict__ lw,
    float* __restrict__ outp)
{
    int idx = blockIdx.x * 256 + threadIdx.x;          // one float4 per thread
    // softmax of the 7 lag weights (tiny, recomputed per thread; L1-cached)
    float w[LL]; float mx = -1e30f, sum = 0.f;
#pragma unroll
    for (int l = 0; l < LL; l++) { w[l] = __ldg(&lw[l]); mx = fmaxf(mx, w[l]); }
#pragma unroll
    for (int l = 0; l < LL; l++) { w[l] = __expf(w[l] - mx); sum += w[l]; }
    float inv = 1.f / sum;

    int row = idx >> 7;                 // (b*N + n), 128 float4 per row
    int c4  = (idx & 127) << 2;
    size_t base = (size_t)row * LL * DD + c4;
    float ax = 0.f, ay = 0.f, az = 0.f, aw = 0.f;
#pragma unroll
    for (int l = 0; l < LL; l++) {
        float4 v = *reinterpret_cast<const float4*>(&lf[base + (size_t)l * DD]);
        float wl = w[l] * inv;
        ax += wl * v.x; ay += wl * v.y; az += wl * v.z; aw += wl * v.w;
    }
    float4 o = {ax, ay, az, aw};
    *reinterpret_cast<float4*>(&outp[(size_t)row * DD + c4]) = o;
}

// ---------------- kernel 2: generic NT GEMM + bias --------------------------
// C[m, o] = sum_k A[m,k] * W[o,k] + bias[o]       (torch Linear)
// M = 16384, N = K = 512.  128x128x8 tiles, 256 threads, 8x8 per thread,
// inner loop in packed f32x2 (FFMA2).
__global__ void __launch_bounds__(256) gemm_nt_bias_kernel(
    const float* __restrict__ A, const float* __restrict__ W,
    const float* __restrict__ bias, float* __restrict__ C)
{
    __shared__ __align__(16) float As[8][128];
    __shared__ __align__(16) float Ws[8][128];

    const int t    = threadIdx.x;
    const int bm   = blockIdx.y * 128;
    const int bn   = blockIdx.x * 128;
    const int ty   = t >> 4;            // 0..15
    const int tx   = t & 15;            // 0..15
    const int lrow = t >> 1;            // 0..127
    const int lseg = (t & 1) << 2;      // 0 or 4

    const float* Ag = A + (size_t)(bm + lrow) * DD + lseg;
    const float* Wg = W + (size_t)(bn + lrow) * DD + lseg;

    unsigned long long acc[8][4];
#pragma unroll
    for (int i = 0; i < 8; i++)
#pragma unroll
        for (int j = 0; j < 4; j++) acc[i][j] = 0ull;

    for (int k0 = 0; k0 < DD; k0 += 8) {
        float4 av = *reinterpret_cast<const float4*>(Ag + k0);
        float4 wv = *reinterpret_cast<const float4*>(Wg + k0);
        __syncthreads();   // previous iteration's reads complete
        As[lseg + 0][lrow] = av.x; As[lseg + 1][lrow] = av.y;
        As[lseg + 2][lrow] = av.z; As[lseg + 3][lrow] = av.w;
        Ws[lseg + 0][lrow] = wv.x; Ws[lseg + 1][lrow] = wv.y;
        Ws[lseg + 2][lrow] = wv.z; Ws[lseg + 3][lrow] = wv.w;
        __syncthreads();
#pragma unroll
        for (int kk = 0; kk < 8; kk++) {
            float4 a0 = *reinterpret_cast<const float4*>(&As[kk][ty * 8]);
            float4 a1 = *reinterpret_cast<const float4*>(&As[kk][ty * 8 + 4]);
            float4 b0 = *reinterpret_cast<const float4*>(&Ws[kk][tx * 8]);
            float4 b1 = *reinterpret_cast<const float4*>(&Ws[kk][tx * 8 + 4]);
            unsigned long long b2[4] = {
                f32x2_pack(b0.x, b0.y), f32x2_pack(b0.z, b0.w),
                f32x2_pack(b1.x, b1.y), f32x2_pack(b1.z, b1.w)
            };
            float aa[8] = {a0.x, a0.y, a0.z, a0.w, a1.x, a1.y, a1.z, a1.w};
#pragma unroll
            for (int i = 0; i < 8; i++) {
                unsigned long long ad = f32x2_dup(aa[i]);
#pragma unroll
                for (int j = 0; j < 4; j++)
                    acc[i][j] = f32x2_fma(ad, b2[j], acc[i][j]);
            }
        }
    }

    float bvals[8];
#pragma unroll
    for (int j = 0; j < 8; j++) bvals[j] = bias[bn + tx * 8 + j];
#pragma unroll
    for (int i = 0; i < 8; i++) {
        float o[8];
#pragma unroll
        for (int j = 0; j < 4; j++) {
            float lo, hi; f32x2_unpack(acc[i][j], lo, hi);
            o[2 * j]     = lo + bvals[2 * j];
            o[2 * j + 1] = hi + bvals[2 * j + 1];
        }
        float4 v0 = {o[0], o[1], o[2], o[3]};
        float4 v1 = {o[4], o[5], o[6], o[7]};
        float* Cp = C + (size_t)(bm + ty * 8 + i) * DD + bn + tx * 8;
        *reinterpret_cast<float4*>(Cp)     = v0;
        *reinterpret_cast<float4*>(Cp + 4) = v1;
    }
}

// ---------------- kernel 3: flash attention with adjacency bias -------------
// One block = one (b, h) and 64 query rows. 256 threads (16x16), each owns a
// 4x4 tile of the 64x64 score tile and a 4(rows)x4(dims) O accumulator.
// Smem: Qt (transposed+swizzled), KP (K transposed then reused for P^T), V.
__global__ void __launch_bounds__(256) attn_kernel(
    const float* __restrict__ Q, const float* __restrict__ K,
    const float* __restrict__ V, const float* __restrict__ adj,
    float* __restrict__ O)
{
    __shared__ __align__(16) float Qs[64][64];
    __shared__ __align__(16) float KP[64][64];
    __shared__ __align__(16) float Vs[64][64];

    const int t  = threadIdx.x;
    const int ty = t >> 4;          // 0..15 -> query rows 4*ty..
    const int tx = t & 15;          // 0..15 -> key cols / dims 4*tx..
    const int b  = blockIdx.y >> 3;
    const int h  = blockIdx.y & 7;
    const int n0 = blockIdx.x * 64;
    const size_t rowQ0 = (size_t)b * NN + n0;

    // ---- load Q tile, transposed + swizzled, pre-scaled by 1/sqrt(HD) ----
    {
        const int r  = t >> 4;
        const int cs = (t & 15) << 2;
#pragma unroll
        for (int it = 0; it < 4; it++) {
            int rr = r + it * 16;
            float4 v = *reinterpret_cast<const float4*>(
                &Q[(rowQ0 + rr) * DD + h * HD + cs]);
            float vv[4] = {v.x, v.y, v.z, v.w};
#pragma unroll
            for (int e = 0; e < 4; e++) {
                int d = cs + e;
                Qs[d][rr ^ ((d >> 2) << 2)] = vv[e] * 0.125f;
            }
        }
    }

    unsigned long long o2[4][2];
    float m_i[4], l_i[4];
#pragma unroll
    for (int i = 0; i < 4; i++) {
        o2[i][0] = 0ull; o2[i][1] = 0ull;
        m_i[i] = -1e30f; l_i[i] = 0.f;
    }

    const unsigned long long HALF2 = 0x3F0000003F000000ULL; // {0.5f, 0.5f}

    for (int kt = 0; kt < 16; kt++) {
        __syncthreads();    // previous PV reads / Q writes complete
        // ---- load K (transposed+swizzled) and V (row-major) tiles ----
        {
            const int r  = t >> 4;
            const int cs = (t & 15) << 2;
            const size_t rowK0 = (size_t)b * NN + kt * 64;
#pragma unroll
            for (int it = 0; it < 4; it++) {
                int rr = r + it * 16;
                float4 kv = *reinterpret_cast<const float4*>(
                    &K[(rowK0 + rr) * DD + h * HD + cs]);
                float4 vv = *reinterpret_cast<const float4*>(
                    &V[(rowK0 + rr) * DD + h * HD + cs]);
                float ka[4] = {kv.x, kv.y, kv.z, kv.w};
#pragma unroll
                for (int e = 0; e < 4; e++) {
                    int d = cs + e;
                    KP[d][rr ^ ((d >> 2) << 2)] = ka[e];
                }
                *reinterpret_cast<float4*>(&Vs[rr][cs]) = vv;
            }
        }
        __syncthreads();

        // ---- S = (Q/8) . K^T  (packed over key-column pairs) ----
        unsigned long long s2[4][2];
#pragma unroll
        for (int i = 0; i < 4; i++) { s2[i][0] = 0ull; s2[i][1] = 0ull; }
#pragma unroll 4
        for (int d = 0; d < 64; d++) {
            int sw = (d >> 2) << 2;
            float4 q4 = *reinterpret_cast<const float4*>(&Qs[d][(ty << 2) ^ sw]);
            float4 k4 = *reinterpret_cast<const float4*>(&KP[d][(tx << 2) ^ sw]);
            unsigned long long kb0 = f32x2_pack(k4.x, k4.y);
            unsigned long long kb1 = f32x2_pack(k4.z, k4.w);
            float qa[4] = {q4.x, q4.y, q4.z, q4.w};
#pragma unroll
            for (int i = 0; i < 4; i++) {
                unsigned long long qd = f32x2_dup(qa[i]);
                s2[i][0] = f32x2_fma(qd, kb0, s2[i][0]);
                s2[i][1] = f32x2_fma(qd, kb1, s2[i][1]);
            }
        }

        // ---- add 0.5 * adj_prior bias (packed float2 global loads) ----
#pragma unroll
        for (int i = 0; i < 4; i++) {
            size_t arow = (size_t)(n0 + ty * 4 + i) * NN + kt * 64 + tx * 4;
#pragma unroll
            for (int j = 0; j < 2; j++) {
                unsigned long long a2 = *reinterpret_cast<const unsigned long long*>(
                    &adj[arow + 2 * j]);
                s2[i][j] = f32x2_fma(a2, HALF2, s2[i][j]);
            }
        }

        float s[4][4];
#pragma unroll
        for (int i = 0; i < 4; i++) {
            f32x2_unpack(s2[i][0], s[i][0], s[i][1]);
            f32x2_unpack(s2[i][1], s[i][2], s[i][3]);
        }

        // ---- online softmax (row reductions over the 16 tx lanes) ----
        float p[4][4];
#pragma unroll
        for (int i = 0; i < 4; i++) {
            float rm = fmaxf(fmaxf(s[i][0], s[i][1]), fmaxf(s[i][2], s[i][3]));
            rm = fmaxf(rm, __shfl_xor_sync(0xffffffffu, rm, 1));
            rm = fmaxf(rm, __shfl_xor_sync(0xffffffffu, rm, 2));
            rm = fmaxf(rm, __shfl_xor_sync(0xffffffffu, rm, 4));
            rm = fmaxf(rm, __shfl_xor_sync(0xffffffffu, rm, 8));
            float mn    = fmaxf(m_i[i], rm);
            float alpha = __expf(m_i[i] - mn);
            m_i[i] = mn;
            float rs = 0.f;
#pragma unroll
            for (int jj = 0; jj < 4; jj++) {
                p[i][jj] = __expf(s[i][jj] - mn);
                rs += p[i][jj];
            }
            rs += __shfl_xor_sync(0xffffffffu, rs, 1);
            rs += __shfl_xor_sync(0xffffffffu, rs, 2);
            rs += __shfl_xor_sync(0xffffffffu, rs, 4);
            rs += __shfl_xor_sync(0xffffffffu, rs, 8);
            l_i[i] = l_i[i] * alpha + rs;
            unsigned long long ad = f32x2_dup(alpha);
            o2[i][0] = f32x2_mul(o2[i][0], ad);
            o2[i][1] = f32x2_mul(o2[i][1], ad);
        }

        __syncthreads();   // everyone done reading K tile
        // ---- store P transposed + swizzled into the K buffer ----
#pragma unroll
        for (int jj = 0; jj < 4; jj++) {
            int c = tx * 4 + jj;
#pragma unroll
            for (int i = 0; i < 4; i++)
                KP[c][(ty * 4 + i) ^ (tx << 2)] = p[i][jj];
        }
        __syncthreads();

        // ---- O += P^T-tile . V  (packed over dim pairs) ----
#pragma unroll 4
        for (int k = 0; k < 64; k++) {
            float4 p4 = *reinterpret_cast<const float4*>(
                &KP[k][(ty << 2) ^ ((k >> 2) << 2)]);
            float4 v4 = *reinterpret_cast<const float4*>(&Vs[k][tx << 2]);
            unsigned long long vb0 = f32x2_pack(v4.x, v4.y);
            unsigned long long vb1 = f32x2_pack(v4.z, v4.w);
            float pa[4] = {p4.x, p4.y, p4.z, p4.w};
#pragma unroll
            for (int i = 0; i < 4; i++) {
                unsigned long long pd = f32x2_dup(pa[i]);
                o2[i][0] = f32x2_fma(pd, vb0, o2[i][0]);
                o2[i][1] = f32x2_fma(pd, vb1, o2[i][1]);
            }
        }
    }

    // ---- epilogue: normalize and write out (b, n, h*64 + hd) ----
#pragma unroll
    for (int i = 0; i < 4; i++) {
        float inv = 1.0f / l_i[i];
        float o[4];
        f32x2_unpack(o2[i][0], o[0], o[1]);
        f32x2_unpack(o2[i][1], o[2], o[3]);
        float4 ov = {o[0] * inv, o[1] * inv, o[2] * inv, o[3] * inv};
        *reinterpret_cast<float4*>(
            &O[(rowQ0 + ty * 4 + i) * DD + h * HD + tx * 4]) = ov;
    }
}

// ---------------- kernel 4: residual + LayerNorm -----------------------------
__global__ void __launch_bounds__(256) ln_kernel(
    const float* __restrict__ cur, const float* __restrict__ proj,
    const float* __restrict__ g, const float* __restrict__ bta,
    float* __restrict__ out)
{
    const int m = blockIdx.x;
    const int t = threadIdx.x;
    const float2 c2 = *reinterpret_cast<const float2*>(&cur[(size_t)m * DD + t * 2]);
    const float2 p2 = *reinterpret_cast<const float2*>(&proj[(size_t)m * DD + t * 2]);
    float x0 = c2.x + p2.x, x1 = c2.y + p2.y;
    float s = x0 + x1;
    float q = x0 * x0 + x1 * x1;
#pragma unroll
    for (int off = 16; off; off >>= 1) {
        s += __shfl_xor_sync(0xffffffffu, s, off);
        q += __shfl_xor_sync(0xffffffffu, q, off);
    }
    __shared__ float ss[8], qq[8];
    int w = t >> 5, lane = t & 31;
    if (lane == 0) { ss[w] = s; qq[w] = q; }
    __syncthreads();
    if (w == 0) {
        float s2 = (lane < 8) ? ss[lane] : 0.f;
        float q2 = (lane < 8) ? qq[lane] : 0.f;
#pragma unroll
        for (int off = 4; off; off >>= 1) {
            s2 += __shfl_xor_sync(0xffffffffu, s2, off);
            q2 += __shfl_xor_sync(0xffffffffu, q2, off);
        }
        if (lane == 0) { ss[0] = s2; qq[0] = q2; }
    }
    __syncthreads();
    const float mu  = ss[0] * (1.f / 512.f);
    const float var = qq[0] * (1.f / 512.f) - mu * mu;
    const float r   = rsqrtf(var + 1e-5f);
    const float2 g2 = *reinterpret_cast<const float2*>(&g[t * 2]);
    const float2 b2 = *reinterpret_cast<const float2*>(&bta[t * 2]);
    float2 o;
    o.x = (x0 - mu) * r * g2.x + b2.x;
    o.y = (x1 - mu) * r * g2.y + b2.y;
    *reinterpret_cast<float2*>(&out[(size_t)m * DD + t * 2]) = o;
}

// ---------------- launcher ---------------------------------------------------
extern "C" void kernel_launch(void* const* d_in, const int* in_sizes, int n_in,
                              void* d_out, int out_size)
{
    (void)in_sizes; (void)n_in; (void)out_size;
    const float* cur = (const float*)d_in[0];
    const float* lf  = (const float*)d_in[1];
    const float* lw  = (const float*)d_in[2];
    const float* Wq  = (const float*)d_in[3];
    const float* bq  = (const float*)d_in[4];
    const float* Wk  = (const float*)d_in[5];
    const float* bk  = (const float*)d_in[6];
    const float* Wv  = (const float*)d_in[7];
    const float* bv  = (const float*)d_in[8];
    const float* Wo  = (const float*)d_in[9];
    const float* bo  = (const float*)d_in[10];
    const float* adj = (const float*)d_in[11];
    const float* lng = (const float*)d_in[12];
    const float* lnb = (const float*)d_in[13];
    float* out = (float*)d_out;

    float *agg, *Qb, *Kb, *Vb, *att;
    cudaGetSymbolAddress((void**)&agg, g_agg);
    cudaGetSymbolAddress((void**)&Qb,  g_Q);
    cudaGetSymbolAddress((void**)&Kb,  g_K);
    cudaGetSymbolAddress((void**)&Vb,  g_V);
    cudaGetSymbolAddress((void**)&att, g_att);

    // 1. lag softmax + aggregation
    lag_agg_kernel<<<BND / 4 / 256, 256>>>(lf, lw, agg);

    // 2-4. Q/K/V projections
    dim3 ggrid(DD / 128, (BB * NN) / 128);   // (4, 128)
    gemm_nt_bias_kernel<<<ggrid, 256>>>(cur, Wq, bq, Qb);
    gemm_nt_bias_kernel<<<ggrid, 256>>>(agg, Wk, bk, Kb);
    gemm_nt_bias_kernel<<<ggrid, 256>>>(agg, Wv, bv, Vb);

    // 5. attention with adjacency bias
    attn_kernel<<<dim3(NN / 64, BB * HH), 256>>>(Qb, Kb, Vb, adj, att);

    // 6. output projection (reuse agg buffer)
    gemm_nt_bias_kernel<<<ggrid, 256>>>(att, Wo, bo, agg);

    // 7. residual + layernorm
    ln_kernel<<<BB * NN, 256>>>(cur, agg, lng, lnb, out);
}